// round 1
// baseline (speedup 1.0000x reference)
#include <cuda_runtime.h>
#include <math.h>

#define BATCH 4
#define CH    128
#define HH    128
#define WW    128
#define HWQ   16384           // H*W
#define NHEAD 8
#define NPNT  8
#define NOFF  128             // nh*P*2
#define NATT  64              // nh*P
#define NTOT  192             // NOFF + NATT
#define MAXRES 10.0f

// ---- scratch (static device allocations; no cudaMalloc allowed) ----
__device__ float  d_val [(size_t)BATCH * HWQ * CH];   // (B,Q,C) value-projected features
__device__ float  d_agg [(size_t)BATCH * HWQ * CH];   // (B,Q,C) aggregated
__device__ float2 d_loc [(size_t)BATCH * HWQ * NATT]; // (B,Q,64) sample locations
__device__ float  d_attn[(size_t)BATCH * HWQ * NATT]; // (B,Q,64) softmax weights

// ============================================================================
// Kernel 1: ext @ [W_off|W_attn] -> tanh offsets -> loc ; softmax -> attn
// 64 rows per block, 256 threads, thread tile 4x12 over 64x192
// ============================================================================
__global__ __launch_bounds__(256) void k_off_attn(
    const float* __restrict__ ext, const float* __restrict__ flow,
    const float* __restrict__ W_off, const float* __restrict__ b_off,
    const float* __restrict__ W_attn, const float* __restrict__ b_attn)
{
    __shared__ __align__(16) float sm[32*64 + 32*192];  // 8192 floats = 32KB
    float (*As)[64]  = (float(*)[64])sm;                // [32][64] k-major
    float (*Ws)[192] = (float(*)[192])(sm + 32*64);     // [32][192]

    const int tx   = threadIdx.x;
    const int row0 = blockIdx.x * 64;
    const int b    = row0 / HWQ;
    const int q0   = row0 % HWQ;
    const int r0   = (tx >> 4) * 4;
    const int c0   = (tx & 15) * 12;

    float acc[4][12];
#pragma unroll
    for (int i = 0; i < 4; ++i)
#pragma unroll
        for (int j = 0; j < 12; ++j) acc[i][j] = 0.f;

    for (int k0 = 0; k0 < CH; k0 += 32) {
        for (int idx = tx; idx < 32*64; idx += 256) {
            int k = idx >> 6, r = idx & 63;
            As[k][r] = ext[(size_t)b*CH*HWQ + (size_t)(k0+k)*HWQ + q0 + r];
        }
        for (int idx = tx; idx < 32*NTOT; idx += 256) {
            int k = idx / NTOT, c = idx % NTOT;
            Ws[k][c] = (c < NOFF) ? W_off[(k0+k)*NOFF + c]
                                  : W_attn[(k0+k)*NATT + (c - NOFF)];
        }
        __syncthreads();
#pragma unroll 8
        for (int k = 0; k < 32; ++k) {
            float4 a4 = *(const float4*)&As[k][r0];
            float av[4] = {a4.x, a4.y, a4.z, a4.w};
            float4 w0 = *(const float4*)&Ws[k][c0];
            float4 w1 = *(const float4*)&Ws[k][c0+4];
            float4 w2 = *(const float4*)&Ws[k][c0+8];
            float wv[12] = {w0.x,w0.y,w0.z,w0.w, w1.x,w1.y,w1.z,w1.w, w2.x,w2.y,w2.z,w2.w};
#pragma unroll
            for (int i = 0; i < 4; ++i)
#pragma unroll
                for (int j = 0; j < 12; ++j) acc[i][j] = fmaf(av[i], wv[j], acc[i][j]);
        }
        __syncthreads();
    }

    // ---- epilogue pass A: offsets -> loc ----
    float (*obuf)[NOFF] = (float(*)[NOFF])sm;          // [64][128] = 32KB (reuse)
#pragma unroll
    for (int i = 0; i < 4; ++i)
#pragma unroll
        for (int j = 0; j < 12; ++j) {
            int c = c0 + j;
            if (c < NOFF) obuf[r0+i][c] = acc[i][j];
        }
    __syncthreads();
#pragma unroll
    for (int t = 0; t < 16; ++t) {
        int idx = tx + t*256;              // 4096 = 64 rows * 64 (h,p) pairs
        int r = idx >> 6, n = idx & 63;
        int qq = q0 + r;
        float ox = MAXRES * tanhf(obuf[r][2*n]   + b_off[2*n]);
        float oy = MAXRES * tanhf(obuf[r][2*n+1] + b_off[2*n+1]);
        float fx = flow[(size_t)b*2*HWQ + qq];
        float fy = flow[(size_t)b*2*HWQ + HWQ + qq];
        int wi = qq & (WW-1), hi = qq >> 7;
        float lx = (wi + 0.5f)*(1.f/WW) + (fx + ox)*(1.f/WW);
        float ly = (hi + 0.5f)*(1.f/HH) + (fy + oy)*(1.f/HH);
        d_loc[((size_t)b*HWQ + qq)*NATT + n] = make_float2(lx, ly);
    }
    __syncthreads();

    // ---- epilogue pass B: attention softmax ----
    float (*abuf)[NATT] = (float(*)[NATT])sm;          // [64][64] = 16KB (reuse)
#pragma unroll
    for (int i = 0; i < 4; ++i)
#pragma unroll
        for (int j = 0; j < 12; ++j) {
            int c = c0 + j;
            if (c >= NOFF) abuf[r0+i][c - NOFF] = acc[i][j];
        }
    __syncthreads();
#pragma unroll
    for (int t = 0; t < 2; ++t) {
        int idx = tx + t*256;              // 512 = 64 rows * 8 heads
        int r = idx >> 3, h = idx & 7;
        int qq = q0 + r;
        float l[NPNT], m = -1e30f;
#pragma unroll
        for (int p = 0; p < NPNT; ++p) {
            l[p] = abuf[r][h*NPNT + p] + b_attn[h*NPNT + p];
            m = fmaxf(m, l[p]);
        }
        float s = 0.f;
#pragma unroll
        for (int p = 0; p < NPNT; ++p) { l[p] = expf(l[p] - m); s += l[p]; }
        float inv = 1.f / s;
#pragma unroll
        for (int p = 0; p < NPNT; ++p)
            d_attn[((size_t)b*HWQ + qq)*NATT + h*NPNT + p] = l[p] * inv;
    }
}

// ============================================================================
// Kernel 2: val = nbr @ W_val + b_val  -> d_val (B,Q,C)
// 64 rows/block, 256 threads, thread tile 4x8 over 64x128
// ============================================================================
__global__ __launch_bounds__(256) void k_val(
    const float* __restrict__ nbr,
    const float* __restrict__ W_val, const float* __restrict__ b_val)
{
    __shared__ __align__(16) float sm[32*64 + 32*128]; // 6144 floats = 24KB
    float (*As)[64]  = (float(*)[64])sm;
    float (*Ws)[128] = (float(*)[128])(sm + 32*64);

    const int tx   = threadIdx.x;
    const int row0 = blockIdx.x * 64;
    const int b    = row0 / HWQ;
    const int q0   = row0 % HWQ;
    const int r0   = (tx >> 4) * 4;
    const int c0   = (tx & 15) * 8;

    float acc[4][8];
#pragma unroll
    for (int i = 0; i < 4; ++i)
#pragma unroll
        for (int j = 0; j < 8; ++j) acc[i][j] = 0.f;

    for (int k0 = 0; k0 < CH; k0 += 32) {
        for (int idx = tx; idx < 32*64; idx += 256) {
            int k = idx >> 6, r = idx & 63;
            As[k][r] = nbr[(size_t)b*CH*HWQ + (size_t)(k0+k)*HWQ + q0 + r];
        }
        for (int idx = tx; idx < 32*128; idx += 256) {
            int k = idx >> 7, c = idx & 127;
            Ws[k][c] = W_val[(k0+k)*CH + c];
        }
        __syncthreads();
#pragma unroll 8
        for (int k = 0; k < 32; ++k) {
            float4 a4 = *(const float4*)&As[k][r0];
            float av[4] = {a4.x, a4.y, a4.z, a4.w};
            float4 w0 = *(const float4*)&Ws[k][c0];
            float4 w1 = *(const float4*)&Ws[k][c0+4];
            float wv[8] = {w0.x,w0.y,w0.z,w0.w, w1.x,w1.y,w1.z,w1.w};
#pragma unroll
            for (int i = 0; i < 4; ++i)
#pragma unroll
                for (int j = 0; j < 8; ++j) acc[i][j] = fmaf(av[i], wv[j], acc[i][j]);
        }
        __syncthreads();
    }

    float4 bv0 = *(const float4*)&b_val[c0];
    float4 bv1 = *(const float4*)&b_val[c0+4];
#pragma unroll
    for (int i = 0; i < 4; ++i) {
        size_t base = (size_t)(row0 + r0 + i)*CH + c0;
        float4 o0 = make_float4(acc[i][0]+bv0.x, acc[i][1]+bv0.y, acc[i][2]+bv0.z, acc[i][3]+bv0.w);
        float4 o1 = make_float4(acc[i][4]+bv1.x, acc[i][5]+bv1.y, acc[i][6]+bv1.z, acc[i][7]+bv1.w);
        *(float4*)&d_val[base]   = o0;
        *(float4*)&d_val[base+4] = o1;
    }
}

// ============================================================================
// Kernel 3: bilinear gather + attention-weighted aggregation -> d_agg (B,Q,C)
// Block = 256 threads handles 2 q positions; thread = (q_local, channel)
// ============================================================================
__global__ __launch_bounds__(256) void k_gather()
{
    __shared__ float2 loc_s[2][NATT];
    __shared__ float  attn_s[2][NATT];
    const int tx = threadIdx.x;
    const int pair0 = blockIdx.x * 2;       // global (b*Q+q) base

    if (tx < 128) {
        int tq = tx >> 6, n = tx & 63;
        loc_s[tq][n]  = d_loc [(size_t)(pair0 + tq)*NATT + n];
        attn_s[tq][n] = d_attn[(size_t)(pair0 + tq)*NATT + n];
    }
    __syncthreads();

    const int tq  = tx >> 7;
    const int c   = tx & 127;
    const int h   = c >> 4;
    const int row = pair0 + tq;
    const int b   = row >> 14;              // / HWQ
    const size_t vbase = (size_t)b * HWQ * CH;

    float acc = 0.f;
#pragma unroll
    for (int p = 0; p < NPNT; ++p) {
        int n = h*NPNT + p;
        float2 l = loc_s[tq][n];
        float  a = attn_s[tq][n];
        float x = l.x * (float)WW - 0.5f;
        float y = l.y * (float)HH - 0.5f;
        float x0f = floorf(x), y0f = floorf(y);
        float wx = x - x0f,    wy = y - y0f;
        int x0 = (int)x0f, y0 = (int)y0f;
        int x1 = x0 + 1,   y1 = y0 + 1;
        bool xv0 = (x0 >= 0) & (x0 < WW);
        bool xv1 = (x1 >= 0) & (x1 < WW);
        bool yv0 = (y0 >= 0) & (y0 < HH);
        bool yv1 = (y1 >= 0) & (y1 < HH);
        float w00 = (1.f-wx)*(1.f-wy) * a;
        float w10 = wx*(1.f-wy) * a;
        float w01 = (1.f-wx)*wy * a;
        float w11 = wx*wy * a;
        if (xv0 & yv0) acc = fmaf(w00, d_val[vbase + (size_t)(y0*WW + x0)*CH + c], acc);
        if (xv1 & yv0) acc = fmaf(w10, d_val[vbase + (size_t)(y0*WW + x1)*CH + c], acc);
        if (xv0 & yv1) acc = fmaf(w01, d_val[vbase + (size_t)(y1*WW + x0)*CH + c], acc);
        if (xv1 & yv1) acc = fmaf(w11, d_val[vbase + (size_t)(y1*WW + x1)*CH + c], acc);
    }
    d_agg[(size_t)row*CH + c] = acc;
}

// ============================================================================
// Kernel 4: out = agg @ W_out + b_out, written transposed to (B,C,H,W)
// ============================================================================
__global__ __launch_bounds__(256) void k_out(
    const float* __restrict__ W_out, const float* __restrict__ b_out,
    float* __restrict__ out)
{
    __shared__ __align__(16) float sm[64*129];          // 8256 floats = 33KB
    float (*As)[33]  = (float(*)[33])sm;                // [64][33] row-major A (padded)
    float (*Ws)[128] = (float(*)[128])(sm + 64*33);     // [32][128]

    const int tx   = threadIdx.x;
    const int row0 = blockIdx.x * 64;
    const int b    = row0 / HWQ;
    const int q0   = row0 % HWQ;
    const int r0   = (tx >> 4) * 4;
    const int c0   = (tx & 15) * 8;

    float acc[4][8];
#pragma unroll
    for (int i = 0; i < 4; ++i)
#pragma unroll
        for (int j = 0; j < 8; ++j) acc[i][j] = 0.f;

    for (int k0 = 0; k0 < CH; k0 += 32) {
        for (int idx = tx; idx < 64*32; idx += 256) {
            int r = idx >> 5, k = idx & 31;
            As[r][k] = d_agg[(size_t)(row0 + r)*CH + k0 + k];
        }
        for (int idx = tx; idx < 32*128; idx += 256) {
            int k = idx >> 7, c = idx & 127;
            Ws[k][c] = W_out[(k0+k)*CH + c];
        }
        __syncthreads();
#pragma unroll 8
        for (int k = 0; k < 32; ++k) {
            float av[4];
#pragma unroll
            for (int i = 0; i < 4; ++i) av[i] = As[r0+i][k];
            float4 w0 = *(const float4*)&Ws[k][c0];
            float4 w1 = *(const float4*)&Ws[k][c0+4];
            float wv[8] = {w0.x,w0.y,w0.z,w0.w, w1.x,w1.y,w1.z,w1.w};
#pragma unroll
            for (int i = 0; i < 4; ++i)
#pragma unroll
                for (int j = 0; j < 8; ++j) acc[i][j] = fmaf(av[i], wv[j], acc[i][j]);
        }
        __syncthreads();
    }

    // stage with bias into padded smem, then transposed coalesced store
    float (*buf)[129] = (float(*)[129])sm;
#pragma unroll
    for (int i = 0; i < 4; ++i)
#pragma unroll
        for (int j = 0; j < 8; ++j)
            buf[r0+i][c0+j] = acc[i][j] + b_out[c0+j];
    __syncthreads();
    for (int idx = tx; idx < 64*128; idx += 256) {
        int n = idx >> 6, r = idx & 63;
        out[(size_t)b*CH*HWQ + (size_t)n*HWQ + q0 + r] = buf[r][n];
    }
}

// ============================================================================
extern "C" void kernel_launch(void* const* d_in, const int* in_sizes, int n_in,
                              void* d_out, int out_size)
{
    const float* nbr    = (const float*)d_in[0];
    const float* ext    = (const float*)d_in[1];
    const float* flow   = (const float*)d_in[2];
    const float* W_off  = (const float*)d_in[3];
    const float* b_off  = (const float*)d_in[4];
    const float* W_attn = (const float*)d_in[5];
    const float* b_attn = (const float*)d_in[6];
    const float* W_val  = (const float*)d_in[7];
    const float* b_val  = (const float*)d_in[8];
    const float* W_out  = (const float*)d_in[9];
    const float* b_out  = (const float*)d_in[10];
    float* out = (float*)d_out;

    const int nrowblk = BATCH * HWQ / 64;   // 1024

    k_off_attn<<<nrowblk, 256>>>(ext, flow, W_off, b_off, W_attn, b_attn);
    k_val     <<<nrowblk, 256>>>(nbr, W_val, b_val);
    k_gather  <<<BATCH * HWQ / 2, 256>>>();
    k_out     <<<nrowblk, 256>>>(W_out, b_out, out);
}

// round 2
// speedup vs baseline: 1.0004x; 1.0004x over previous
#include <cuda_runtime.h>
#include <math.h>

#define BATCH 4
#define CH    128
#define HH    128
#define WW    128
#define HWQ   16384           // H*W
#define NHEAD 8
#define NPNT  8
#define NOFF  128             // nh*P*2
#define NATT  64              // nh*P
#define NTOT  192             // NOFF + NATT
#define MAXRES 10.0f

// ---- scratch (static device allocations; no cudaMalloc allowed) ----
__device__ float  d_val [(size_t)BATCH * HWQ * CH];   // (B,Q,C) value-projected features
__device__ float  d_agg [(size_t)BATCH * HWQ * CH];   // (B,Q,C) aggregated
__device__ float2 d_loc [(size_t)BATCH * HWQ * NATT]; // (B,Q,64) sample locations
__device__ float  d_attn[(size_t)BATCH * HWQ * NATT]; // (B,Q,64) softmax weights

// ============================================================================
// Kernel 1: ext @ [W_off|W_attn] -> tanh offsets -> loc ; softmax -> attn
// 64 rows per block, 256 threads, thread tile 4x12 over 64x192
// ============================================================================
__global__ __launch_bounds__(256) void k_off_attn(
    const float* __restrict__ ext, const float* __restrict__ flow,
    const float* __restrict__ W_off, const float* __restrict__ b_off,
    const float* __restrict__ W_attn, const float* __restrict__ b_attn)
{
    __shared__ __align__(16) float sm[32*64 + 32*192];  // 8192 floats = 32KB
    float (*As)[64]  = (float(*)[64])sm;                // [32][64] k-major
    float (*Ws)[192] = (float(*)[192])(sm + 32*64);     // [32][192]

    const int tx   = threadIdx.x;
    const int row0 = blockIdx.x * 64;
    const int b    = row0 / HWQ;
    const int q0   = row0 % HWQ;
    const int r0   = (tx >> 4) * 4;
    const int c0   = (tx & 15) * 12;

    float acc[4][12];
#pragma unroll
    for (int i = 0; i < 4; ++i)
#pragma unroll
        for (int j = 0; j < 12; ++j) acc[i][j] = 0.f;

    for (int k0 = 0; k0 < CH; k0 += 32) {
        for (int idx = tx; idx < 32*64; idx += 256) {
            int k = idx >> 6, r = idx & 63;
            As[k][r] = ext[(size_t)b*CH*HWQ + (size_t)(k0+k)*HWQ + q0 + r];
        }
        for (int idx = tx; idx < 32*NTOT; idx += 256) {
            int k = idx / NTOT, c = idx % NTOT;
            Ws[k][c] = (c < NOFF) ? W_off[(k0+k)*NOFF + c]
                                  : W_attn[(k0+k)*NATT + (c - NOFF)];
        }
        __syncthreads();
#pragma unroll 8
        for (int k = 0; k < 32; ++k) {
            float4 a4 = *(const float4*)&As[k][r0];
            float av[4] = {a4.x, a4.y, a4.z, a4.w};
            float4 w0 = *(const float4*)&Ws[k][c0];
            float4 w1 = *(const float4*)&Ws[k][c0+4];
            float4 w2 = *(const float4*)&Ws[k][c0+8];
            float wv[12] = {w0.x,w0.y,w0.z,w0.w, w1.x,w1.y,w1.z,w1.w, w2.x,w2.y,w2.z,w2.w};
#pragma unroll
            for (int i = 0; i < 4; ++i)
#pragma unroll
                for (int j = 0; j < 12; ++j) acc[i][j] = fmaf(av[i], wv[j], acc[i][j]);
        }
        __syncthreads();
    }

    // ---- epilogue pass A: offsets -> loc ----
    float (*obuf)[NOFF] = (float(*)[NOFF])sm;          // [64][128] = 32KB (reuse)
#pragma unroll
    for (int i = 0; i < 4; ++i)
#pragma unroll
        for (int j = 0; j < 12; ++j) {
            int c = c0 + j;
            if (c < NOFF) obuf[r0+i][c] = acc[i][j];
        }
    __syncthreads();
#pragma unroll
    for (int t = 0; t < 16; ++t) {
        int idx = tx + t*256;              // 4096 = 64 rows * 64 (h,p) pairs
        int r = idx >> 6, n = idx & 63;
        int qq = q0 + r;
        float ox = MAXRES * tanhf(obuf[r][2*n]   + b_off[2*n]);
        float oy = MAXRES * tanhf(obuf[r][2*n+1] + b_off[2*n+1]);
        float fx = flow[(size_t)b*2*HWQ + qq];
        float fy = flow[(size_t)b*2*HWQ + HWQ + qq];
        int wi = qq & (WW-1), hi = qq >> 7;
        float lx = (wi + 0.5f)*(1.f/WW) + (fx + ox)*(1.f/WW);
        float ly = (hi + 0.5f)*(1.f/HH) + (fy + oy)*(1.f/HH);
        d_loc[((size_t)b*HWQ + qq)*NATT + n] = make_float2(lx, ly);
    }
    __syncthreads();

    // ---- epilogue pass B: attention softmax ----
    float (*abuf)[NATT] = (float(*)[NATT])sm;          // [64][64] = 16KB (reuse)
#pragma unroll
    for (int i = 0; i < 4; ++i)
#pragma unroll
        for (int j = 0; j < 12; ++j) {
            int c = c0 + j;
            if (c >= NOFF) abuf[r0+i][c - NOFF] = acc[i][j];
        }
    __syncthreads();
#pragma unroll
    for (int t = 0; t < 2; ++t) {
        int idx = tx + t*256;              // 512 = 64 rows * 8 heads
        int r = idx >> 3, h = idx & 7;
        int qq = q0 + r;
        float l[NPNT], m = -1e30f;
#pragma unroll
        for (int p = 0; p < NPNT; ++p) {
            l[p] = abuf[r][h*NPNT + p] + b_attn[h*NPNT + p];
            m = fmaxf(m, l[p]);
        }
        float s = 0.f;
#pragma unroll
        for (int p = 0; p < NPNT; ++p) { l[p] = expf(l[p] - m); s += l[p]; }
        float inv = 1.f / s;
#pragma unroll
        for (int p = 0; p < NPNT; ++p)
            d_attn[((size_t)b*HWQ + qq)*NATT + h*NPNT + p] = l[p] * inv;
    }
}

// ============================================================================
// Kernel 2: val = nbr @ W_val + b_val  -> d_val (B,Q,C)
// 64 rows/block, 256 threads, thread tile 4x8 over 64x128
// ============================================================================
__global__ __launch_bounds__(256) void k_val(
    const float* __restrict__ nbr,
    const float* __restrict__ W_val, const float* __restrict__ b_val)
{
    __shared__ __align__(16) float sm[32*64 + 32*128]; // 6144 floats = 24KB
    float (*As)[64]  = (float(*)[64])sm;
    float (*Ws)[128] = (float(*)[128])(sm + 32*64);

    const int tx   = threadIdx.x;
    const int row0 = blockIdx.x * 64;
    const int b    = row0 / HWQ;
    const int q0   = row0 % HWQ;
    const int r0   = (tx >> 4) * 4;
    const int c0   = (tx & 15) * 8;

    float acc[4][8];
#pragma unroll
    for (int i = 0; i < 4; ++i)
#pragma unroll
        for (int j = 0; j < 8; ++j) acc[i][j] = 0.f;

    for (int k0 = 0; k0 < CH; k0 += 32) {
        for (int idx = tx; idx < 32*64; idx += 256) {
            int k = idx >> 6, r = idx & 63;
            As[k][r] = nbr[(size_t)b*CH*HWQ + (size_t)(k0+k)*HWQ + q0 + r];
        }
        for (int idx = tx; idx < 32*128; idx += 256) {
            int k = idx >> 7, c = idx & 127;
            Ws[k][c] = W_val[(k0+k)*CH + c];
        }
        __syncthreads();
#pragma unroll 8
        for (int k = 0; k < 32; ++k) {
            float4 a4 = *(const float4*)&As[k][r0];
            float av[4] = {a4.x, a4.y, a4.z, a4.w};
            float4 w0 = *(const float4*)&Ws[k][c0];
            float4 w1 = *(const float4*)&Ws[k][c0+4];
            float wv[8] = {w0.x,w0.y,w0.z,w0.w, w1.x,w1.y,w1.z,w1.w};
#pragma unroll
            for (int i = 0; i < 4; ++i)
#pragma unroll
                for (int j = 0; j < 8; ++j) acc[i][j] = fmaf(av[i], wv[j], acc[i][j]);
        }
        __syncthreads();
    }

    float4 bv0 = *(const float4*)&b_val[c0];
    float4 bv1 = *(const float4*)&b_val[c0+4];
#pragma unroll
    for (int i = 0; i < 4; ++i) {
        size_t base = (size_t)(row0 + r0 + i)*CH + c0;
        float4 o0 = make_float4(acc[i][0]+bv0.x, acc[i][1]+bv0.y, acc[i][2]+bv0.z, acc[i][3]+bv0.w);
        float4 o1 = make_float4(acc[i][4]+bv1.x, acc[i][5]+bv1.y, acc[i][6]+bv1.z, acc[i][7]+bv1.w);
        *(float4*)&d_val[base]   = o0;
        *(float4*)&d_val[base+4] = o1;
    }
}

// ============================================================================
// Kernel 3: bilinear gather + attention-weighted aggregation -> d_agg (B,Q,C)
// Block = 256 threads handles 2 q positions; thread = (q_local, channel)
// ============================================================================
__global__ __launch_bounds__(256) void k_gather()
{
    __shared__ float2 loc_s[2][NATT];
    __shared__ float  attn_s[2][NATT];
    const int tx = threadIdx.x;
    const int pair0 = blockIdx.x * 2;       // global (b*Q+q) base

    if (tx < 128) {
        int tq = tx >> 6, n = tx & 63;
        loc_s[tq][n]  = d_loc [(size_t)(pair0 + tq)*NATT + n];
        attn_s[tq][n] = d_attn[(size_t)(pair0 + tq)*NATT + n];
    }
    __syncthreads();

    const int tq  = tx >> 7;
    const int c   = tx & 127;
    const int h   = c >> 4;
    const int row = pair0 + tq;
    const int b   = row >> 14;              // / HWQ
    const size_t vbase = (size_t)b * HWQ * CH;

    float acc = 0.f;
#pragma unroll
    for (int p = 0; p < NPNT; ++p) {
        int n = h*NPNT + p;
        float2 l = loc_s[tq][n];
        float  a = attn_s[tq][n];
        float x = l.x * (float)WW - 0.5f;
        float y = l.y * (float)HH - 0.5f;
        float x0f = floorf(x), y0f = floorf(y);
        float wx = x - x0f,    wy = y - y0f;
        int x0 = (int)x0f, y0 = (int)y0f;
        int x1 = x0 + 1,   y1 = y0 + 1;
        bool xv0 = (x0 >= 0) & (x0 < WW);
        bool xv1 = (x1 >= 0) & (x1 < WW);
        bool yv0 = (y0 >= 0) & (y0 < HH);
        bool yv1 = (y1 >= 0) & (y1 < HH);
        float w00 = (1.f-wx)*(1.f-wy) * a;
        float w10 = wx*(1.f-wy) * a;
        float w01 = (1.f-wx)*wy * a;
        float w11 = wx*wy * a;
        if (xv0 & yv0) acc = fmaf(w00, d_val[vbase + (size_t)(y0*WW + x0)*CH + c], acc);
        if (xv1 & yv0) acc = fmaf(w10, d_val[vbase + (size_t)(y0*WW + x1)*CH + c], acc);
        if (xv0 & yv1) acc = fmaf(w01, d_val[vbase + (size_t)(y1*WW + x0)*CH + c], acc);
        if (xv1 & yv1) acc = fmaf(w11, d_val[vbase + (size_t)(y1*WW + x1)*CH + c], acc);
    }
    d_agg[(size_t)row*CH + c] = acc;
}

// ============================================================================
// Kernel 4: out = agg @ W_out + b_out, written transposed to (B,C,H,W)
// ============================================================================
__global__ __launch_bounds__(256) void k_out(
    const float* __restrict__ W_out, const float* __restrict__ b_out,
    float* __restrict__ out)
{
    __shared__ __align__(16) float sm[64*129];          // 8256 floats = 33KB
    float (*As)[33]  = (float(*)[33])sm;                // [64][33] row-major A (padded)
    float (*Ws)[128] = (float(*)[128])(sm + 64*33);     // [32][128]

    const int tx   = threadIdx.x;
    const int row0 = blockIdx.x * 64;
    const int b    = row0 / HWQ;
    const int q0   = row0 % HWQ;
    const int r0   = (tx >> 4) * 4;
    const int c0   = (tx & 15) * 8;

    float acc[4][8];
#pragma unroll
    for (int i = 0; i < 4; ++i)
#pragma unroll
        for (int j = 0; j < 8; ++j) acc[i][j] = 0.f;

    for (int k0 = 0; k0 < CH; k0 += 32) {
        for (int idx = tx; idx < 64*32; idx += 256) {
            int r = idx >> 5, k = idx & 31;
            As[r][k] = d_agg[(size_t)(row0 + r)*CH + k0 + k];
        }
        for (int idx = tx; idx < 32*128; idx += 256) {
            int k = idx >> 7, c = idx & 127;
            Ws[k][c] = W_out[(k0+k)*CH + c];
        }
        __syncthreads();
#pragma unroll 8
        for (int k = 0; k < 32; ++k) {
            float av[4];
#pragma unroll
            for (int i = 0; i < 4; ++i) av[i] = As[r0+i][k];
            float4 w0 = *(const float4*)&Ws[k][c0];
            float4 w1 = *(const float4*)&Ws[k][c0+4];
            float wv[8] = {w0.x,w0.y,w0.z,w0.w, w1.x,w1.y,w1.z,w1.w};
#pragma unroll
            for (int i = 0; i < 4; ++i)
#pragma unroll
                for (int j = 0; j < 8; ++j) acc[i][j] = fmaf(av[i], wv[j], acc[i][j]);
        }
        __syncthreads();
    }

    // stage with bias into padded smem, then transposed coalesced store
    float (*buf)[129] = (float(*)[129])sm;
#pragma unroll
    for (int i = 0; i < 4; ++i)
#pragma unroll
        for (int j = 0; j < 8; ++j)
            buf[r0+i][c0+j] = acc[i][j] + b_out[c0+j];
    __syncthreads();
    for (int idx = tx; idx < 64*128; idx += 256) {
        int n = idx >> 6, r = idx & 63;
        out[(size_t)b*CH*HWQ + (size_t)n*HWQ + q0 + r] = buf[r][n];
    }
}

// ============================================================================
extern "C" void kernel_launch(void* const* d_in, const int* in_sizes, int n_in,
                              void* d_out, int out_size)
{
    const float* nbr    = (const float*)d_in[0];
    const float* ext    = (const float*)d_in[1];
    const float* flow   = (const float*)d_in[2];
    const float* W_off  = (const float*)d_in[3];
    const float* b_off  = (const float*)d_in[4];
    const float* W_attn = (const float*)d_in[5];
    const float* b_attn = (const float*)d_in[6];
    const float* W_val  = (const float*)d_in[7];
    const float* b_val  = (const float*)d_in[8];
    const float* W_out  = (const float*)d_in[9];
    const float* b_out  = (const float*)d_in[10];
    float* out = (float*)d_out;

    const int nrowblk = BATCH * HWQ / 64;   // 1024

    k_off_attn<<<nrowblk, 256>>>(ext, flow, W_off, b_off, W_attn, b_attn);
    k_val     <<<nrowblk, 256>>>(nbr, W_val, b_val);
    k_gather  <<<BATCH * HWQ / 2, 256>>>();
    k_out     <<<nrowblk, 256>>>(W_out, b_out, out);
}

// round 4
// speedup vs baseline: 1.2454x; 1.2449x over previous
#include <cuda_runtime.h>
#include <math.h>

#define BATCH 4
#define CH    128
#define HH    128
#define WW    128
#define HWQ   16384           // H*W
#define NHEAD 8
#define NPNT  8
#define NOFF  128             // nh*P*2
#define NATT  64              // nh*P
#define NTOT  192             // NOFF + NATT
#define MAXRES 10.0f

// ---- scratch (static device allocations; no cudaMalloc allowed) ----
__device__ float  d_val [(size_t)BATCH * HWQ * CH];   // (B,Q,C) value-projected features
__device__ float  d_agg [(size_t)BATCH * HWQ * CH];   // (B,Q,C) aggregated
__device__ float2 d_loc [(size_t)BATCH * HWQ * NATT]; // (B,Q,64) sample locations
__device__ float  d_attn[(size_t)BATCH * HWQ * NATT]; // (B,Q,64) softmax weights

// ============================================================================
// Kernel 1: ext @ [W_off|W_attn] -> tanh offsets -> loc ; softmax -> attn
// 128 rows per block, 256 threads, thread tile 8x12 over 128x192
// ============================================================================
__global__ __launch_bounds__(256) void k_off_attn(
    const float* __restrict__ ext, const float* __restrict__ flow,
    const float* __restrict__ W_off, const float* __restrict__ b_off,
    const float* __restrict__ W_attn, const float* __restrict__ b_attn)
{
    __shared__ __align__(16) float sm[32*128 + 32*192];  // 10240 floats = 40KB
    float (*As)[128] = (float(*)[128])sm;                // [32][128] k-major
    float (*Ws)[192] = (float(*)[192])(sm + 32*128);     // [32][192]

    const int tx   = threadIdx.x;
    const int row0 = blockIdx.x * 128;
    const int b    = row0 / HWQ;
    const int q0   = row0 % HWQ;
    const int r0   = (tx >> 4) * 8;
    const int c0   = (tx & 15) * 12;

    float acc[8][12];
#pragma unroll
    for (int i = 0; i < 8; ++i)
#pragma unroll
        for (int j = 0; j < 12; ++j) acc[i][j] = 0.f;

    for (int k0 = 0; k0 < CH; k0 += 32) {
        const float* ebase = ext + ((size_t)b*CH + k0)*HWQ + q0;
        // A: 32x128 floats = 1024 float4, coalesced (r contiguous in gmem & smem)
        for (int i = tx; i < 1024; i += 256) {
            int k = i >> 5, r4 = i & 31;
            ((float4*)As)[k*32 + r4] = __ldg((const float4*)(ebase + (size_t)k*HWQ) + r4);
        }
        // W_off: 32x128 -> first 128 cols
        for (int i = tx; i < 1024; i += 256) {
            int k = i >> 5, c4 = i & 31;
            *(float4*)&Ws[k][c4*4] = __ldg((const float4*)(W_off + (size_t)(k0+k)*NOFF) + c4);
        }
        // W_attn: 32x64 -> cols 128..191
        for (int i = tx; i < 512; i += 256) {
            int k = i >> 4, c4 = i & 15;
            *(float4*)&Ws[k][NOFF + c4*4] = __ldg((const float4*)(W_attn + (size_t)(k0+k)*NATT) + c4);
        }
        __syncthreads();
#pragma unroll 4
        for (int k = 0; k < 32; ++k) {
            float4 a0 = *(const float4*)&As[k][r0];
            float4 a1 = *(const float4*)&As[k][r0+4];
            float av[8] = {a0.x,a0.y,a0.z,a0.w, a1.x,a1.y,a1.z,a1.w};
            float4 w0 = *(const float4*)&Ws[k][c0];
            float4 w1 = *(const float4*)&Ws[k][c0+4];
            float4 w2 = *(const float4*)&Ws[k][c0+8];
            float wv[12] = {w0.x,w0.y,w0.z,w0.w, w1.x,w1.y,w1.z,w1.w, w2.x,w2.y,w2.z,w2.w};
#pragma unroll
            for (int i = 0; i < 8; ++i)
#pragma unroll
                for (int j = 0; j < 12; ++j) acc[i][j] = fmaf(av[i], wv[j], acc[i][j]);
        }
        __syncthreads();
    }

    // ---- epilogue A: offset cols (c<128) -> tanh -> loc, straight from regs.
    // c0 and tile width 12 are even, so (x,y) pairs never straddle threads.
#pragma unroll
    for (int i = 0; i < 8; ++i) {
        if (c0 < NOFF) {
            int qq = q0 + r0 + i;
            float fx = flow[(size_t)b*2*HWQ + qq];
            float fy = flow[(size_t)b*2*HWQ + HWQ + qq];
            int wi = qq & (WW-1), hi = (qq >> 7) & (HH-1);
#pragma unroll
            for (int jp = 0; jp < 6; ++jp) {
                int c = c0 + 2*jp;
                if (c + 1 < NOFF) {
                    int n = c >> 1;
                    float ox = MAXRES * tanhf(acc[i][2*jp]   + b_off[c]);
                    float oy = MAXRES * tanhf(acc[i][2*jp+1] + b_off[c+1]);
                    float lx = (wi + 0.5f + fx + ox) * (1.f/WW);
                    float ly = (hi + 0.5f + fy + oy) * (1.f/HH);
                    d_loc[((size_t)b*HWQ + qq)*NATT + n] = make_float2(lx, ly);
                }
            }
        }
    }

    // ---- epilogue B: attn cols (c>=128) -> smem -> softmax ----
    float (*abuf)[65] = (float(*)[65])sm;        // [128][65] = 33.3KB (reuse)
#pragma unroll
    for (int i = 0; i < 8; ++i)
#pragma unroll
        for (int j = 0; j < 12; ++j) {
            int c = c0 + j;
            if (c >= NOFF) abuf[r0+i][c - NOFF] = acc[i][j];
        }
    __syncthreads();
#pragma unroll
    for (int t = 0; t < 4; ++t) {
        int idx = tx + t*256;                    // 1024 = 128 rows * 8 heads
        int r = idx >> 3, h = idx & 7;
        int qq = q0 + r;
        float l[NPNT], m = -1e30f;
#pragma unroll
        for (int p = 0; p < NPNT; ++p) {
            l[p] = abuf[r][h*NPNT + p] + b_attn[h*NPNT + p];
            m = fmaxf(m, l[p]);
        }
        float s = 0.f;
#pragma unroll
        for (int p = 0; p < NPNT; ++p) { l[p] = __expf(l[p] - m); s += l[p]; }
        float inv = 1.f / s;
#pragma unroll
        for (int p = 0; p < NPNT; ++p)
            d_attn[((size_t)b*HWQ + qq)*NATT + h*NPNT + p] = l[p] * inv;
    }
}

// ============================================================================
// Kernel 2: val = nbr @ W_val + b_val  -> d_val (B,Q,C)
// 128 rows/block, 256 threads, thread tile 8x8 over 128x128
// ============================================================================
__global__ __launch_bounds__(256) void k_val(
    const float* __restrict__ nbr,
    const float* __restrict__ W_val, const float* __restrict__ b_val)
{
    __shared__ __align__(16) float sm[32*128 + 32*128]; // 8192 floats = 32KB
    float (*As)[128] = (float(*)[128])sm;               // k-major
    float (*Ws)[128] = (float(*)[128])(sm + 32*128);

    const int tx   = threadIdx.x;
    const int row0 = blockIdx.x * 128;
    const int b    = row0 / HWQ;
    const int q0   = row0 % HWQ;
    const int r0   = (tx >> 4) * 8;
    const int c0   = (tx & 15) * 8;

    float acc[8][8];
#pragma unroll
    for (int i = 0; i < 8; ++i)
#pragma unroll
        for (int j = 0; j < 8; ++j) acc[i][j] = 0.f;

    for (int k0 = 0; k0 < CH; k0 += 32) {
        const float* nbase = nbr + ((size_t)b*CH + k0)*HWQ + q0;
        for (int i = tx; i < 1024; i += 256) {
            int k = i >> 5, r4 = i & 31;
            ((float4*)As)[k*32 + r4] = __ldg((const float4*)(nbase + (size_t)k*HWQ) + r4);
        }
        for (int i = tx; i < 1024; i += 256) {
            int k = i >> 5, c4 = i & 31;
            *(float4*)&Ws[k][c4*4] = __ldg((const float4*)(W_val + (size_t)(k0+k)*CH) + c4);
        }
        __syncthreads();
#pragma unroll 4
        for (int k = 0; k < 32; ++k) {
            float4 a0 = *(const float4*)&As[k][r0];
            float4 a1 = *(const float4*)&As[k][r0+4];
            float av[8] = {a0.x,a0.y,a0.z,a0.w, a1.x,a1.y,a1.z,a1.w};
            float4 w0 = *(const float4*)&Ws[k][c0];
            float4 w1 = *(const float4*)&Ws[k][c0+4];
            float wv[8] = {w0.x,w0.y,w0.z,w0.w, w1.x,w1.y,w1.z,w1.w};
#pragma unroll
            for (int i = 0; i < 8; ++i)
#pragma unroll
                for (int j = 0; j < 8; ++j) acc[i][j] = fmaf(av[i], wv[j], acc[i][j]);
        }
        __syncthreads();
    }

    float4 bv0 = *(const float4*)&b_val[c0];
    float4 bv1 = *(const float4*)&b_val[c0+4];
#pragma unroll
    for (int i = 0; i < 8; ++i) {
        size_t base = (size_t)(row0 + r0 + i)*CH + c0;
        float4 o0 = make_float4(acc[i][0]+bv0.x, acc[i][1]+bv0.y, acc[i][2]+bv0.z, acc[i][3]+bv0.w);
        float4 o1 = make_float4(acc[i][4]+bv1.x, acc[i][5]+bv1.y, acc[i][6]+bv1.z, acc[i][7]+bv1.w);
        *(float4*)&d_val[base]   = o0;
        *(float4*)&d_val[base+4] = o1;
    }
}

// ============================================================================
// Kernel 3: bilinear gather + attention-weighted aggregation -> d_agg (B,Q,C)
// Block = 256 threads handles 8 q positions; thread = (q_local, 4 channels)
// ============================================================================
__global__ __launch_bounds__(256) void k_gather()
{
    __shared__ float2 loc_s[8][NATT];
    __shared__ float  attn_s[8][NATT];
    const int tx = threadIdx.x;
    const size_t base = (size_t)blockIdx.x * 8;   // global (b*Q+q) base

    for (int i = tx; i < 512; i += 256) {
        int tq = i >> 6, n = i & 63;
        loc_s[tq][n]  = d_loc [(base + tq)*NATT + n];
        attn_s[tq][n] = d_attn[(base + tq)*NATT + n];
    }
    __syncthreads();

    const int tq  = tx >> 5;                // 0..7
    const int c4  = tx & 31;                // float4 group: channels 4c4..4c4+3
    const int h   = c4 >> 2;                // 16 channels (4 float4) per head
    const size_t row = base + tq;
    const int b   = (int)(row >> 14);       // / HWQ
    const float* vb = d_val + (size_t)b * HWQ * CH;

    float4 acc = make_float4(0.f, 0.f, 0.f, 0.f);
#pragma unroll
    for (int p = 0; p < NPNT; ++p) {
        int n = h*NPNT + p;
        float2 l = loc_s[tq][n];
        float  a = attn_s[tq][n];
        float x = l.x * (float)WW - 0.5f;
        float y = l.y * (float)HH - 0.5f;
        float x0f = floorf(x), y0f = floorf(y);
        float wx = x - x0f,    wy = y - y0f;
        int x0 = (int)x0f, y0 = (int)y0f;
        int x1 = x0 + 1,   y1 = y0 + 1;
        bool xv0 = (x0 >= 0) & (x0 < WW);
        bool xv1 = (x1 >= 0) & (x1 < WW);
        bool yv0 = (y0 >= 0) & (y0 < HH);
        bool yv1 = (y1 >= 0) & (y1 < HH);
        float w00 = (1.f-wx)*(1.f-wy) * a;
        float w10 = wx*(1.f-wy) * a;
        float w01 = (1.f-wx)*wy * a;
        float w11 = wx*wy * a;
        if (xv0 & yv0) { float4 g = __ldg((const float4*)(vb + (size_t)(y0*WW + x0)*CH) + c4);
            acc.x=fmaf(w00,g.x,acc.x); acc.y=fmaf(w00,g.y,acc.y); acc.z=fmaf(w00,g.z,acc.z); acc.w=fmaf(w00,g.w,acc.w); }
        if (xv1 & yv0) { float4 g = __ldg((const float4*)(vb + (size_t)(y0*WW + x1)*CH) + c4);
            acc.x=fmaf(w10,g.x,acc.x); acc.y=fmaf(w10,g.y,acc.y); acc.z=fmaf(w10,g.z,acc.z); acc.w=fmaf(w10,g.w,acc.w); }
        if (xv0 & yv1) { float4 g = __ldg((const float4*)(vb + (size_t)(y1*WW + x0)*CH) + c4);
            acc.x=fmaf(w01,g.x,acc.x); acc.y=fmaf(w01,g.y,acc.y); acc.z=fmaf(w01,g.z,acc.z); acc.w=fmaf(w01,g.w,acc.w); }
        if (xv1 & yv1) { float4 g = __ldg((const float4*)(vb + (size_t)(y1*WW + x1)*CH) + c4);
            acc.x=fmaf(w11,g.x,acc.x); acc.y=fmaf(w11,g.y,acc.y); acc.z=fmaf(w11,g.z,acc.z); acc.w=fmaf(w11,g.w,acc.w); }
    }
    *((float4*)(d_agg + row*CH) + c4) = acc;
}

// ============================================================================
// Kernel 4: out = agg @ W_out + b_out, written transposed to (B,C,H,W)
// 128 rows/block, 256 threads, 8x8 thread tile; A row-major [128][36] padded
// (36-float row stride keeps float4 smem stores 16B-aligned; compute reads
// As[r][k] are broadcast so padding choice doesn't cause conflicts)
// ============================================================================
__global__ __launch_bounds__(256) void k_out(
    const float* __restrict__ W_out, const float* __restrict__ b_out,
    float* __restrict__ out)
{
    __shared__ __align__(16) float sm[128*36 + 32*128];  // 4608+4096 floats = 34.8KB
    float (*As)[36]  = (float(*)[36])sm;                 // [128][36] row-major (16B-aligned rows)
    float (*Ws)[128] = (float(*)[128])(sm + 128*36);     // [32][128]

    const int tx   = threadIdx.x;
    const int row0 = blockIdx.x * 128;
    const int b    = row0 / HWQ;
    const int q0   = row0 % HWQ;
    const int r0   = (tx >> 4) * 8;
    const int c0   = (tx & 15) * 8;

    float acc[8][8];
#pragma unroll
    for (int i = 0; i < 8; ++i)
#pragma unroll
        for (int j = 0; j < 8; ++j) acc[i][j] = 0.f;

    for (int k0 = 0; k0 < CH; k0 += 32) {
        // A: 128 rows x 32 k, gmem contiguous in k -> float4 loads
        for (int i = tx; i < 1024; i += 256) {
            int r = i >> 3, c4i = i & 7;
            float4 v = *(const float4*)(d_agg + (size_t)(row0 + r)*CH + k0 + c4i*4);
            *(float4*)&As[r][c4i*4] = v;
        }
        for (int i = tx; i < 1024; i += 256) {
            int k = i >> 5, c4i = i & 31;
            *(float4*)&Ws[k][c4i*4] = __ldg((const float4*)(W_out + (size_t)(k0+k)*CH) + c4i);
        }
        __syncthreads();
#pragma unroll 4
        for (int k = 0; k < 32; ++k) {
            float av[8];
#pragma unroll
            for (int i = 0; i < 8; ++i) av[i] = As[r0+i][k];
            float4 w0 = *(const float4*)&Ws[k][c0];
            float4 w1 = *(const float4*)&Ws[k][c0+4];
            float wv[8] = {w0.x,w0.y,w0.z,w0.w, w1.x,w1.y,w1.z,w1.w};
#pragma unroll
            for (int i = 0; i < 8; ++i)
#pragma unroll
                for (int j = 0; j < 8; ++j) acc[i][j] = fmaf(av[i], wv[j], acc[i][j]);
        }
        __syncthreads();
    }

    // transposed store via smem, 4 chunks of 32 output channels (scalar stores,
    // [33]-stride layout reusing the As region -> conflict-free reads)
    float (*buf)[33] = (float(*)[33])sm;
    float bias[8];
#pragma unroll
    for (int j = 0; j < 8; ++j) bias[j] = b_out[c0 + j];

#pragma unroll
    for (int m = 0; m < 4; ++m) {
        if (((tx & 15) >> 2) == m) {
#pragma unroll
            for (int i = 0; i < 8; ++i)
#pragma unroll
                for (int j = 0; j < 8; ++j)
                    buf[r0+i][c0 + j - 32*m] = acc[i][j] + bias[j];
        }
        __syncthreads();
        for (int idx = tx; idx < 4096; idx += 256) {
            int n = idx >> 7, r = idx & 127;
            out[(size_t)b*CH*HWQ + (size_t)(32*m + n)*HWQ + q0 + r] = buf[r][n];
        }
        __syncthreads();
    }
}

// ============================================================================
extern "C" void kernel_launch(void* const* d_in, const int* in_sizes, int n_in,
                              void* d_out, int out_size)
{
    const float* nbr    = (const float*)d_in[0];
    const float* ext    = (const float*)d_in[1];
    const float* flow   = (const float*)d_in[2];
    const float* W_off  = (const float*)d_in[3];
    const float* b_off  = (const float*)d_in[4];
    const float* W_attn = (const float*)d_in[5];
    const float* b_attn = (const float*)d_in[6];
    const float* W_val  = (const float*)d_in[7];
    const float* b_val  = (const float*)d_in[8];
    const float* W_out  = (const float*)d_in[9];
    const float* b_out  = (const float*)d_in[10];
    float* out = (float*)d_out;

    const int nrowblk = BATCH * HWQ / 128;   // 512

    k_off_attn<<<nrowblk, 256>>>(ext, flow, W_off, b_off, W_attn, b_attn);
    k_val     <<<nrowblk, 256>>>(nbr, W_val, b_val);
    k_gather  <<<BATCH * HWQ / 8, 256>>>();
    k_out     <<<nrowblk, 256>>>(W_out, b_out, out);
}

// round 6
// speedup vs baseline: 1.8319x; 1.4709x over previous
#include <cuda_runtime.h>
#include <math.h>
#include <stdint.h>

#define BATCH 4
#define CH    128
#define HH    128
#define WW    128
#define HWQ   16384
#define NHEAD 8
#define NPNT  8
#define NOFF  128
#define NATT  64
#define MAXRES 10.0f

#define LDA 132        // k-major A tile stride (floats), 128+4 pad
#define LDB128 132
#define LDB192 196

// ---- scratch ----
__device__ float  d_val [(size_t)BATCH * HWQ * CH];
__device__ float  d_agg [(size_t)BATCH * HWQ * CH];
__device__ float2 d_loc [(size_t)BATCH * HWQ * NATT];
__device__ float  d_attn[(size_t)BATCH * HWQ * NATT];

// ============================================================================
// helpers
// ============================================================================
__device__ __forceinline__ void mma_tf32(float* c, uint32_t a0, uint32_t a1,
                                         uint32_t a2, uint32_t a3,
                                         uint32_t b0, uint32_t b1) {
    asm volatile(
        "mma.sync.aligned.m16n8k8.row.col.f32.tf32.tf32.f32 "
        "{%0,%1,%2,%3},{%4,%5,%6,%7},{%8,%9},{%0,%1,%2,%3};"
        : "+f"(c[0]), "+f"(c[1]), "+f"(c[2]), "+f"(c[3])
        : "r"(a0), "r"(a1), "r"(a2), "r"(a3), "r"(b0), "r"(b1));
}

// hi = exact top-10-mantissa part (tf32-exact), lo = residual
__device__ __forceinline__ void split2(float v, float& h, float& l) {
    h = __uint_as_float(__float_as_uint(v) & 0xFFFFE000u);
    l = v - h;
}

// round-to-nearest tf32 (unbiased single-operand rounding)
__device__ __forceinline__ float tf32_rna(float f) {
    uint32_t r;
    asm("cvt.rna.tf32.f32 %0, %1;" : "=r"(r) : "f"(f));
    return __uint_as_float(r);
}

__device__ __forceinline__ uint32_t fb(float f) { return __float_as_uint(f); }

// ============================================================================
// Kernel 1: ext @ [W_off|W_attn]  (M=128/block, N=192, K=128)
// tf32 3-pass split (AhBh + AlBh + AhBl) ~ fp32 accuracy.
// 8 warps: mw = w&3 (32 rows), nw = w>>2 (96 cols). Epilogue fused.
// ============================================================================
__global__ __launch_bounds__(256) void k1_offattn(
    const float* __restrict__ ext, const float* __restrict__ flow,
    const float* __restrict__ W_off, const float* __restrict__ b_off,
    const float* __restrict__ W_attn, const float* __restrict__ b_attn)
{
    extern __shared__ float sm[];
    float* AH = sm;                    // 32*132
    float* AL = AH + 32*LDA;
    float* BH = AL + 32*LDA;           // 32*196
    float* BL = BH + 32*LDB192;

    const int tid  = threadIdx.x;
    const int lane = tid & 31;
    const int warp = tid >> 5;
    const int mw   = warp & 3;
    const int nw   = warp >> 2;
    const int g    = lane >> 2;        // fragment group (row within 8)
    const int tq   = lane & 3;         // thread-in-group (k / col-pair sel)
    const int row0 = blockIdx.x * 128;
    const int b    = row0 / HWQ;
    const int q0   = row0 % HWQ;

    float acc[2][12][4];
#pragma unroll
    for (int t = 0; t < 2; ++t)
#pragma unroll
        for (int j = 0; j < 12; ++j)
#pragma unroll
            for (int v = 0; v < 4; ++v) acc[t][j][v] = 0.f;

    for (int kc = 0; kc < 4; ++kc) {
        // ---- stage A (ext is (C, HWQ): k rows, m contiguous) ----
        {
            const int m4 = (tid & 31) * 4;
            const int kb = tid >> 5;
            const float* src = ext + ((size_t)b*CH + kc*32)*HWQ + q0;
#pragma unroll
            for (int it = 0; it < 4; ++it) {
                int k = kb + it*8;
                float4 v = __ldg((const float4*)(src + (size_t)k*HWQ + m4));
                float4 h, l;
                split2(v.x, h.x, l.x); split2(v.y, h.y, l.y);
                split2(v.z, h.z, l.z); split2(v.w, h.w, l.w);
                *(float4*)(AH + k*LDA + m4) = h;
                *(float4*)(AL + k*LDA + m4) = l;
            }
        }
        // ---- stage B = [W_off | W_attn], k-major, 192 cols ----
#pragma unroll
        for (int it = 0; it < 6; ++it) {
            int idx = tid + it*256;            // < 1536
            int k = idx / 48, f4 = idx % 48;
            const float* srcp = (f4 < 32)
                ? W_off  + (size_t)(kc*32 + k)*NOFF + f4*4
                : W_attn + (size_t)(kc*32 + k)*NATT + (f4-32)*4;
            float4 v = __ldg((const float4*)srcp);
            float4 h, l;
            split2(v.x, h.x, l.x); split2(v.y, h.y, l.y);
            split2(v.z, h.z, l.z); split2(v.w, h.w, l.w);
            *(float4*)(BH + k*LDB192 + f4*4) = h;
            *(float4*)(BL + k*LDB192 + f4*4) = l;
        }
        __syncthreads();

#pragma unroll
        for (int k8 = 0; k8 < 4; ++k8) {
            const int kr = k8*8 + tq;
            uint32_t ah[2][4], al[2][4];
#pragma unroll
            for (int t = 0; t < 2; ++t) {
                int m = mw*32 + t*16 + g;
                ah[t][0] = fb(AH[kr*LDA + m]);     ah[t][1] = fb(AH[kr*LDA + m + 8]);
                ah[t][2] = fb(AH[(kr+4)*LDA + m]); ah[t][3] = fb(AH[(kr+4)*LDA + m + 8]);
                al[t][0] = fb(AL[kr*LDA + m]);     al[t][1] = fb(AL[kr*LDA + m + 8]);
                al[t][2] = fb(AL[(kr+4)*LDA + m]); al[t][3] = fb(AL[(kr+4)*LDA + m + 8]);
            }
            uint32_t bh[12][2], bl[12][2];
#pragma unroll
            for (int j = 0; j < 12; ++j) {
                int n = nw*96 + j*8 + g;
                bh[j][0] = fb(BH[kr*LDB192 + n]); bh[j][1] = fb(BH[(kr+4)*LDB192 + n]);
                bl[j][0] = fb(BL[kr*LDB192 + n]); bl[j][1] = fb(BL[(kr+4)*LDB192 + n]);
            }
#pragma unroll
            for (int t = 0; t < 2; ++t)
#pragma unroll
                for (int j = 0; j < 12; ++j) {
                    mma_tf32(acc[t][j], ah[t][0],ah[t][1],ah[t][2],ah[t][3], bh[j][0],bh[j][1]);
                    mma_tf32(acc[t][j], al[t][0],al[t][1],al[t][2],al[t][3], bh[j][0],bh[j][1]);
                    mma_tf32(acc[t][j], ah[t][0],ah[t][1],ah[t][2],ah[t][3], bl[j][0],bl[j][1]);
                }
        }
        __syncthreads();
    }

    // ---- epilogue: rows held by this thread ----
    int   qrow[4]; float fxv[4], fyv[4]; float wiv[4], hiv[4];
#pragma unroll
    for (int t = 0; t < 2; ++t)
#pragma unroll
        for (int rr = 0; rr < 2; ++rr) {
            int r  = mw*32 + t*16 + g + rr*8;
            int qq = q0 + r;
            int ri = t*2 + rr;
            qrow[ri] = qq;
            fxv[ri] = __ldg(&flow[(size_t)b*2*HWQ + qq]);
            fyv[ri] = __ldg(&flow[(size_t)b*2*HWQ + HWQ + qq]);
            wiv[ri] = (float)(qq & (WW-1));
            hiv[ri] = (float)((qq >> 7) & (HH-1));
        }

#pragma unroll
    for (int j = 0; j < 12; ++j) {
        int c = nw*96 + j*8 + 2*tq;     // warp-uniform branch boundary (per j)
        if (c < NOFF) {
            int n = c >> 1;
            float b0v = __ldg(&b_off[c]), b1v = __ldg(&b_off[c+1]);
#pragma unroll
            for (int t = 0; t < 2; ++t)
#pragma unroll
                for (int rr = 0; rr < 2; ++rr) {
                    int ri = t*2 + rr;
                    float ox = MAXRES * tanhf(acc[t][j][rr*2]   + b0v);
                    float oy = MAXRES * tanhf(acc[t][j][rr*2+1] + b1v);
                    float lx = (wiv[ri] + 0.5f + fxv[ri] + ox) * (1.f/WW);
                    float ly = (hiv[ri] + 0.5f + fyv[ri] + oy) * (1.f/HH);
                    d_loc[((size_t)b*HWQ + qrow[ri])*NATT + n] = make_float2(lx, ly);
                }
        } else {
            int ca = c - NOFF;
            float ba0 = __ldg(&b_attn[ca]), ba1 = __ldg(&b_attn[ca+1]);
#pragma unroll
            for (int t = 0; t < 2; ++t)
#pragma unroll
                for (int rr = 0; rr < 2; ++rr) {
                    float v0 = acc[t][j][rr*2]   + ba0;
                    float v1 = acc[t][j][rr*2+1] + ba1;
                    float mx = fmaxf(v0, v1);
                    mx = fmaxf(mx, __shfl_xor_sync(0xffffffffu, mx, 1));
                    mx = fmaxf(mx, __shfl_xor_sync(0xffffffffu, mx, 2));
                    float e0 = __expf(v0 - mx), e1 = __expf(v1 - mx);
                    float s = e0 + e1;
                    s += __shfl_xor_sync(0xffffffffu, s, 1);
                    s += __shfl_xor_sync(0xffffffffu, s, 2);
                    float inv = 1.f / s;
                    *(float2*)&d_attn[((size_t)b*HWQ + qrow[t*2+rr])*NATT + ca] =
                        make_float2(e0*inv, e1*inv);
                }
        }
    }
}

// ============================================================================
// Kernel 2: val = nbr @ W_val + b_val  (N=128), tf32 2-pass (A split, B rna)
// ============================================================================
__global__ __launch_bounds__(256) void k_val(
    const float* __restrict__ nbr,
    const float* __restrict__ W_val, const float* __restrict__ b_val)
{
    extern __shared__ float sm[];
    float* AH = sm;
    float* AL = AH + 32*LDA;
    float* BS = AL + 32*LDA;

    const int tid  = threadIdx.x;
    const int lane = tid & 31;
    const int warp = tid >> 5;
    const int mw   = warp & 3;
    const int nw   = warp >> 2;
    const int g    = lane >> 2;
    const int tq   = lane & 3;
    const int row0 = blockIdx.x * 128;
    const int b    = row0 / HWQ;
    const int q0   = row0 % HWQ;

    float acc[2][8][4];
#pragma unroll
    for (int t = 0; t < 2; ++t)
#pragma unroll
        for (int j = 0; j < 8; ++j)
#pragma unroll
            for (int v = 0; v < 4; ++v) acc[t][j][v] = 0.f;

    for (int kc = 0; kc < 4; ++kc) {
        {
            const int m4 = (tid & 31) * 4;
            const int kb = tid >> 5;
            const float* src = nbr + ((size_t)b*CH + kc*32)*HWQ + q0;
#pragma unroll
            for (int it = 0; it < 4; ++it) {
                int k = kb + it*8;
                float4 v = __ldg((const float4*)(src + (size_t)k*HWQ + m4));
                float4 h, l;
                split2(v.x, h.x, l.x); split2(v.y, h.y, l.y);
                split2(v.z, h.z, l.z); split2(v.w, h.w, l.w);
                *(float4*)(AH + k*LDA + m4) = h;
                *(float4*)(AL + k*LDA + m4) = l;
            }
        }
#pragma unroll
        for (int it = 0; it < 4; ++it) {
            int idx = tid + it*256;           // < 1024
            int k = idx >> 5, f4 = idx & 31;
            float4 v = __ldg((const float4*)(W_val + (size_t)(kc*32 + k)*CH + f4*4));
            v.x = tf32_rna(v.x); v.y = tf32_rna(v.y);
            v.z = tf32_rna(v.z); v.w = tf32_rna(v.w);
            *(float4*)(BS + k*LDB128 + f4*4) = v;
        }
        __syncthreads();

#pragma unroll
        for (int k8 = 0; k8 < 4; ++k8) {
            const int kr = k8*8 + tq;
            uint32_t ah[2][4], al[2][4];
#pragma unroll
            for (int t = 0; t < 2; ++t) {
                int m = mw*32 + t*16 + g;
                ah[t][0] = fb(AH[kr*LDA + m]);     ah[t][1] = fb(AH[kr*LDA + m + 8]);
                ah[t][2] = fb(AH[(kr+4)*LDA + m]); ah[t][3] = fb(AH[(kr+4)*LDA + m + 8]);
                al[t][0] = fb(AL[kr*LDA + m]);     al[t][1] = fb(AL[kr*LDA + m + 8]);
                al[t][2] = fb(AL[(kr+4)*LDA + m]); al[t][3] = fb(AL[(kr+4)*LDA + m + 8]);
            }
            uint32_t bs[8][2];
#pragma unroll
            for (int j = 0; j < 8; ++j) {
                int n = nw*64 + j*8 + g;
                bs[j][0] = fb(BS[kr*LDB128 + n]); bs[j][1] = fb(BS[(kr+4)*LDB128 + n]);
            }
#pragma unroll
            for (int t = 0; t < 2; ++t)
#pragma unroll
                for (int j = 0; j < 8; ++j) {
                    mma_tf32(acc[t][j], ah[t][0],ah[t][1],ah[t][2],ah[t][3], bs[j][0],bs[j][1]);
                    mma_tf32(acc[t][j], al[t][0],al[t][1],al[t][2],al[t][3], bs[j][0],bs[j][1]);
                }
        }
        __syncthreads();
    }

#pragma unroll
    for (int j = 0; j < 8; ++j) {
        int c = nw*64 + j*8 + 2*tq;
        float b0v = __ldg(&b_val[c]), b1v = __ldg(&b_val[c+1]);
#pragma unroll
        for (int t = 0; t < 2; ++t)
#pragma unroll
            for (int rr = 0; rr < 2; ++rr) {
                int r = row0 + mw*32 + t*16 + g + rr*8;
                *(float2*)&d_val[(size_t)r*CH + c] =
                    make_float2(acc[t][j][rr*2] + b0v, acc[t][j][rr*2+1] + b1v);
            }
    }
}

// ============================================================================
// Kernel 3: bilinear gather + attention aggregation (unchanged from R3)
// ============================================================================
__global__ __launch_bounds__(256) void k_gather()
{
    __shared__ float2 loc_s[8][NATT];
    __shared__ float  attn_s[8][NATT];
    const int tx = threadIdx.x;
    const size_t base = (size_t)blockIdx.x * 8;

    for (int i = tx; i < 512; i += 256) {
        int tg = i >> 6, n = i & 63;
        loc_s[tg][n]  = d_loc [(base + tg)*NATT + n];
        attn_s[tg][n] = d_attn[(base + tg)*NATT + n];
    }
    __syncthreads();

    const int tg  = tx >> 5;
    const int c4  = tx & 31;
    const int h   = c4 >> 2;
    const size_t row = base + tg;
    const int b   = (int)(row >> 14);
    const float* vb = d_val + (size_t)b * HWQ * CH;

    float4 acc = make_float4(0.f, 0.f, 0.f, 0.f);
#pragma unroll
    for (int p = 0; p < NPNT; ++p) {
        int n = h*NPNT + p;
        float2 l = loc_s[tg][n];
        float  a = attn_s[tg][n];
        float x = l.x * (float)WW - 0.5f;
        float y = l.y * (float)HH - 0.5f;
        float x0f = floorf(x), y0f = floorf(y);
        float wx = x - x0f,    wy = y - y0f;
        int x0 = (int)x0f, y0 = (int)y0f;
        int x1 = x0 + 1,   y1 = y0 + 1;
        bool xv0 = (x0 >= 0) & (x0 < WW);
        bool xv1 = (x1 >= 0) & (x1 < WW);
        bool yv0 = (y0 >= 0) & (y0 < HH);
        bool yv1 = (y1 >= 0) & (y1 < HH);
        float w00 = (1.f-wx)*(1.f-wy) * a;
        float w10 = wx*(1.f-wy) * a;
        float w01 = (1.f-wx)*wy * a;
        float w11 = wx*wy * a;
        if (xv0 & yv0) { float4 gg = __ldg((const float4*)(vb + (size_t)(y0*WW + x0)*CH) + c4);
            acc.x=fmaf(w00,gg.x,acc.x); acc.y=fmaf(w00,gg.y,acc.y); acc.z=fmaf(w00,gg.z,acc.z); acc.w=fmaf(w00,gg.w,acc.w); }
        if (xv1 & yv0) { float4 gg = __ldg((const float4*)(vb + (size_t)(y0*WW + x1)*CH) + c4);
            acc.x=fmaf(w10,gg.x,acc.x); acc.y=fmaf(w10,gg.y,acc.y); acc.z=fmaf(w10,gg.z,acc.z); acc.w=fmaf(w10,gg.w,acc.w); }
        if (xv0 & yv1) { float4 gg = __ldg((const float4*)(vb + (size_t)(y1*WW + x0)*CH) + c4);
            acc.x=fmaf(w01,gg.x,acc.x); acc.y=fmaf(w01,gg.y,acc.y); acc.z=fmaf(w01,gg.z,acc.z); acc.w=fmaf(w01,gg.w,acc.w); }
        if (xv1 & yv1) { float4 gg = __ldg((const float4*)(vb + (size_t)(y1*WW + x1)*CH) + c4);
            acc.x=fmaf(w11,gg.x,acc.x); acc.y=fmaf(w11,gg.y,acc.y); acc.z=fmaf(w11,gg.z,acc.z); acc.w=fmaf(w11,gg.w,acc.w); }
    }
    *((float4*)(d_agg + row*CH) + c4) = acc;
}

// ============================================================================
// Kernel 4: out = agg @ W_out + b_out, transposed store (N=128)
// tf32 2-pass; epilogue via ld-129 smem buffer for coalesced transposed stores
// ============================================================================
__global__ __launch_bounds__(256) void k_out(
    const float* __restrict__ W_out, const float* __restrict__ b_out,
    float* __restrict__ out)
{
    extern __shared__ float sm[];
    float* AH = sm;
    float* AL = AH + 32*LDA;
    float* BS = AL + 32*LDA;

    const int tid  = threadIdx.x;
    const int lane = tid & 31;
    const int warp = tid >> 5;
    const int mw   = warp & 3;
    const int nw   = warp >> 2;
    const int g    = lane >> 2;
    const int tq   = lane & 3;
    const int row0 = blockIdx.x * 128;
    const int b    = row0 / HWQ;
    const int q0   = row0 % HWQ;

    float acc[2][8][4];
#pragma unroll
    for (int t = 0; t < 2; ++t)
#pragma unroll
        for (int j = 0; j < 8; ++j)
#pragma unroll
            for (int v = 0; v < 4; ++v) acc[t][j][v] = 0.f;

    for (int kc = 0; kc < 4; ++kc) {
        // A from d_agg (m-major, k contiguous): transpose into k-major smem
        {
            const int m  = tid & 127;
            const int g0 = tid >> 7;
            const float* src = d_agg + (size_t)(row0 + m)*CH + kc*32;
#pragma unroll
            for (int it = 0; it < 4; ++it) {
                int gg = g0 + it*2;            // 0..7 float4 groups of k
                float4 v = *(const float4*)(src + gg*4);
                float h, l;
                split2(v.x, h, l); AH[(gg*4+0)*LDA + m] = h; AL[(gg*4+0)*LDA + m] = l;
                split2(v.y, h, l); AH[(gg*4+1)*LDA + m] = h; AL[(gg*4+1)*LDA + m] = l;
                split2(v.z, h, l); AH[(gg*4+2)*LDA + m] = h; AL[(gg*4+2)*LDA + m] = l;
                split2(v.w, h, l); AH[(gg*4+3)*LDA + m] = h; AL[(gg*4+3)*LDA + m] = l;
            }
        }
#pragma unroll
        for (int it = 0; it < 4; ++it) {
            int idx = tid + it*256;
            int k = idx >> 5, f4 = idx & 31;
            float4 v = __ldg((const float4*)(W_out + (size_t)(kc*32 + k)*CH + f4*4));
            v.x = tf32_rna(v.x); v.y = tf32_rna(v.y);
            v.z = tf32_rna(v.z); v.w = tf32_rna(v.w);
            *(float4*)(BS + k*LDB128 + f4*4) = v;
        }
        __syncthreads();

#pragma unroll
        for (int k8 = 0; k8 < 4; ++k8) {
            const int kr = k8*8 + tq;
            uint32_t ah[2][4], al[2][4];
#pragma unroll
            for (int t = 0; t < 2; ++t) {
                int m = mw*32 + t*16 + g;
                ah[t][0] = fb(AH[kr*LDA + m]);     ah[t][1] = fb(AH[kr*LDA + m + 8]);
                ah[t][2] = fb(AH[(kr+4)*LDA + m]); ah[t][3] = fb(AH[(kr+4)*LDA + m + 8]);
                al[t][0] = fb(AL[kr*LDA + m]);     al[t][1] = fb(AL[kr*LDA + m + 8]);
                al[t][2] = fb(AL[(kr+4)*LDA + m]); al[t][3] = fb(AL[(kr+4)*LDA + m + 8]);
            }
            uint32_t bs[8][2];
#pragma unroll
            for (int j = 0; j < 8; ++j) {
                int n = nw*64 + j*8 + g;
                bs[j][0] = fb(BS[kr*LDB128 + n]); bs[j][1] = fb(BS[(kr+4)*LDB128 + n]);
            }
#pragma unroll
            for (int t = 0; t < 2; ++t)
#pragma unroll
                for (int j = 0; j < 8; ++j) {
                    mma_tf32(acc[t][j], ah[t][0],ah[t][1],ah[t][2],ah[t][3], bs[j][0],bs[j][1]);
                    mma_tf32(acc[t][j], al[t][0],al[t][1],al[t][2],al[t][3], bs[j][0],bs[j][1]);
                }
        }
        __syncthreads();
    }

    // stage (acc + bias) into buf[m][129], then coalesced transposed store
    float* buf = sm;                       // reuse; 128*129 = 16512 floats
#pragma unroll
    for (int j = 0; j < 8; ++j) {
        int c = nw*64 + j*8 + 2*tq;
        float b0v = __ldg(&b_out[c]), b1v = __ldg(&b_out[c+1]);
#pragma unroll
        for (int t = 0; t < 2; ++t)
#pragma unroll
            for (int rr = 0; rr < 2; ++rr) {
                int m = mw*32 + t*16 + g + rr*8;
                buf[m*129 + c]     = acc[t][j][rr*2]   + b0v;
                buf[m*129 + c + 1] = acc[t][j][rr*2+1] + b1v;
            }
    }
    __syncthreads();
    for (int idx = tid; idx < 128*128; idx += 256) {
        int m = idx & 127, n = idx >> 7;
        out[(size_t)b*CH*HWQ + (size_t)n*HWQ + q0 + m] = buf[m*129 + n];
    }
}

// ============================================================================
extern "C" void kernel_launch(void* const* d_in, const int* in_sizes, int n_in,
                              void* d_out, int out_size)
{
    const float* nbr    = (const float*)d_in[0];
    const float* ext    = (const float*)d_in[1];
    const float* flow   = (const float*)d_in[2];
    const float* W_off  = (const float*)d_in[3];
    const float* b_off  = (const float*)d_in[4];
    const float* W_attn = (const float*)d_in[5];
    const float* b_attn = (const float*)d_in[6];
    const float* W_val  = (const float*)d_in[7];
    const float* b_val  = (const float*)d_in[8];
    const float* W_out  = (const float*)d_in[9];
    const float* b_out  = (const float*)d_in[10];
    float* out = (float*)d_out;

    const int SM_K1 = (2*32*LDA + 2*32*LDB192) * 4;              // 83968
    const int SM_KV = (2*32*LDA + 32*LDB128) * 4;                // 50688
    const int SM_KO_MMA = (2*32*LDA + 32*LDB128) * 4;
    const int SM_KO_BUF = 128*129*4;                              // 66048
    const int SM_KO = SM_KO_BUF > SM_KO_MMA ? SM_KO_BUF : SM_KO_MMA;

    cudaFuncSetAttribute(k1_offattn, cudaFuncAttributeMaxDynamicSharedMemorySize, SM_K1);
    cudaFuncSetAttribute(k_val,      cudaFuncAttributeMaxDynamicSharedMemorySize, SM_KV);
    cudaFuncSetAttribute(k_out,      cudaFuncAttributeMaxDynamicSharedMemorySize, SM_KO);

    const int nblk = BATCH * HWQ / 128;   // 512

    k1_offattn<<<nblk, 256, SM_K1>>>(ext, flow, W_off, b_off, W_attn, b_attn);
    k_val     <<<nblk, 256, SM_KV>>>(nbr, W_val, b_val);
    k_gather  <<<BATCH * HWQ / 8, 256>>>();
    k_out     <<<nblk, 256, SM_KO>>>(W_out, b_out, out);
}